// round 4
// baseline (speedup 1.0000x reference)
#include <cuda_runtime.h>
#include <stdint.h>

#define N_ROWS   32768
#define K_CODES  8192
#define DIM      64
#define DP       (DIM / 2)    // 32 float2 per row
#define BM       128          // rows per CTA
#define BK       32           // codes per k-tile
#define TH       256
#define XS_STRIDE 33          // float2 row stride (pad 1) -> conflict-free row-per-lane loads

// Precomputed ||c_k||^2
__device__ float g_csq[K_CODES];

__global__ void csq_kernel(const float* __restrict__ cb) {
    int k = blockIdx.x * blockDim.x + threadIdx.x;
    if (k >= K_CODES) return;
    const float2* row = reinterpret_cast<const float2*>(cb + (size_t)k * DIM);
    float s = 0.f;
#pragma unroll
    for (int i = 0; i < DP; i++) {
        float2 v = row[i];
        s = fmaf(v.x, v.x, s);
        s = fmaf(v.y, v.y, s);
    }
    g_csq[k] = s;
}

__global__ void vq_kernel(const float* __restrict__ x,
                          const float* __restrict__ cb,
                          float* __restrict__ out) {
    // x tile: [BM][XS_STRIDE] float2 (padded)  -> 33792 B
    // c tile: [BK][DP] float2                  ->  8192 B   (total 41984 B < 48K)
    __shared__ float2 xs[BM * XS_STRIDE];
    __shared__ float2 cs[BK * DP];

    const int tid  = threadIdx.x;
    const int lane = tid & 31;
    const int w    = tid >> 5;       // warp id 0..7 -> column group
    const int col0 = w * 4;          // this warp's 4 codes within the tile (warp-uniform)
    const int gn0  = blockIdx.x * BM;

    // Fill x tile (coalesced global float2 reads)
    {
        const float2* gx = reinterpret_cast<const float2*>(x + (size_t)gn0 * DIM);
#pragma unroll
        for (int u = 0; u < (BM * DP) / TH; u++) {       // 16 iters
            int idx = u * TH + tid;
            int row = idx >> 5;                          // /DP
            int p   = idx & 31;
            xs[row * XS_STRIDE + p] = gx[idx];
        }
    }

    // Per-thread running argmin: thread covers rows {lane + 32*i}, i=0..3
    float best[4];
    int   bidx[4];
#pragma unroll
    for (int i = 0; i < 4; i++) { best[i] = 3.4e38f; bidx[i] = 0; }

    for (int kt = 0; kt < K_CODES / BK; kt++) {
        __syncthreads();    // protect cs reuse (and xs fill on first iter)
        {
            const float2* gc = reinterpret_cast<const float2*>(cb + (size_t)kt * BK * DIM);
#pragma unroll
            for (int u = 0; u < (BK * DP) / TH; u++) {   // 4 iters
                int idx = u * TH + tid;
                cs[idx] = gc[idx];
            }
        }
        float cq[4];
#pragma unroll
        for (int j = 0; j < 4; j++)
            cq[j] = __ldg(&g_csq[kt * BK + col0 + j]);   // warp-uniform, L1-resident
        __syncthreads();

        float acc[4][4];
#pragma unroll
        for (int i = 0; i < 4; i++)
#pragma unroll
            for (int j = 0; j < 4; j++) acc[i][j] = 0.f;

        // Main FMA loop: a-loads conflict-free (distinct lanes -> distinct rows,
        // odd float2 stride), b-loads warp-uniform -> smem broadcast (no bandwidth).
#pragma unroll 8
        for (int p = 0; p < DP; p++) {
            float2 a[4], b[4];
#pragma unroll
            for (int i = 0; i < 4; i++) a[i] = xs[(lane + 32 * i) * XS_STRIDE + p];
#pragma unroll
            for (int j = 0; j < 4; j++) b[j] = cs[(col0 + j) * DP + p];
#pragma unroll
            for (int i = 0; i < 4; i++)
#pragma unroll
                for (int j = 0; j < 4; j++) {
                    acc[i][j] = fmaf(a[i].x, b[j].x, acc[i][j]);
                    acc[i][j] = fmaf(a[i].y, b[j].y, acc[i][j]);
                }
        }

        const int gk0 = kt * BK + col0;
#pragma unroll
        for (int i = 0; i < 4; i++) {
#pragma unroll
            for (int j = 0; j < 4; j++) {
                float s = fmaf(-2.f, acc[i][j], cq[j]);  // ||c||^2 - 2 x.c
                // strict <, j ascending (ascending code index), kt ascending:
                // keeps FIRST minimum like jnp.argmin
                if (s < best[i]) { best[i] = s; bidx[i] = gk0 + j; }
            }
        }
    }

    // Cross-warp reduction: 8 column-group candidates per row. Reuse xs memory.
    __syncthreads();
    float* rv = reinterpret_cast<float*>(xs);           // [BM][8] floats (4 KB)
    int*   ri = reinterpret_cast<int*>(xs) + BM * 8;    // [BM][8] ints   (4 KB)
#pragma unroll
    for (int i = 0; i < 4; i++) {
        int r = lane + 32 * i;
        rv[r * 8 + w] = best[i];
        ri[r * 8 + w] = bidx[i];
    }
    __syncthreads();

    if (tid < BM) {
        float bv = rv[tid * 8];
        int   bi = ri[tid * 8];
#pragma unroll
        for (int c = 1; c < 8; c++) {
            float v  = rv[tid * 8 + c];
            int   ix = ri[tid * 8 + c];
            if (v < bv || (v == bv && ix < bi)) { bv = v; bi = ix; }
        }
        // Output dtype is float32 (indices <= 8191 are exactly representable).
        out[gn0 + tid] = (float)bi;
    }
}

extern "C" void kernel_launch(void* const* d_in, const int* in_sizes, int n_in,
                              void* d_out, int out_size) {
    const float* x  = (const float*)d_in[0];
    const float* cb = (const float*)d_in[1];
    // Defensive: identify operands by size in case metadata order differs.
    if (n_in >= 2 && in_sizes[0] == K_CODES * DIM && in_sizes[1] == N_ROWS * DIM) {
        const float* t = x; x = cb; cb = t;
    }
    float* out = (float*)d_out;

    csq_kernel<<<K_CODES / 256, 256>>>(cb);
    vq_kernel<<<N_ROWS / BM, TH>>>(x, cb, out);
}

// round 5
// speedup vs baseline: 1.0505x; 1.0505x over previous
#include <cuda_runtime.h>
#include <stdint.h>
#include <float.h>

#define N_ROWS   32768
#define K_CODES  8192
#define DIM      64
#define DP       (DIM / 2)    // 32 d-pairs per row
#define BM       128          // rows per CTA
#define BK       64           // codes per k-tile
#define TH       256

// Precomputed ||c_k||^2
__device__ float g_csq[K_CODES];

__global__ void csq_kernel(const float* __restrict__ cb) {
    int k = blockIdx.x * blockDim.x + threadIdx.x;
    if (k >= K_CODES) return;
    const float2* row = reinterpret_cast<const float2*>(cb + (size_t)k * DIM);
    float s = 0.f;
#pragma unroll
    for (int i = 0; i < DP; i++) {
        float2 v = row[i];
        s = fmaf(v.x, v.x, s);
        s = fmaf(v.y, v.y, s);
    }
    g_csq[k] = s;
}

// Packed f32x2 FMA: d = a*b + d (elementwise on (lo,hi) fp32 pairs)
__device__ __forceinline__ void ffma2(unsigned long long& d,
                                      unsigned long long a,
                                      unsigned long long b) {
    asm("fma.rn.f32x2 %0, %1, %2, %0;" : "+l"(d) : "l"(a), "l"(b));
}

__device__ __forceinline__ unsigned long long pack2(float lo, float hi) {
    unsigned long long r;
    asm("mov.b64 %0, {%1, %2};" : "=l"(r) : "f"(lo), "f"(hi));
    return r;
}

__global__ __launch_bounds__(TH, 2)
void vq_kernel(const float* __restrict__ x,
               const float* __restrict__ cb,
               float* __restrict__ out) {
    // Transposed tiles (d-pair major). Exactly 48 KB static smem.
    __shared__ unsigned long long xs[DP * BM];   // xs[p][row]  32768 B
    __shared__ unsigned long long cs[DP * BK];   // cs[p][c]    16384 B

    const int tid    = threadIdx.x;
    const int lane   = tid & 31;
    const int w      = tid >> 5;        // warp 0..7 -> 16-row block
    const int colgrp = lane & 7;        // 0..7  -> column lane
    const int rowgrp = lane >> 3;       // 0..3  -> row sub-block
    const int row0   = w * 16 + rowgrp * 4;   // this thread's 4 rows (contiguous)
    const int gn0    = blockIdx.x * BM;

    // ---- Fill x tile: xs[p][row]. Conflict-free smem writes (lanes -> consecutive rows).
    {
        const float4* gx4 = reinterpret_cast<const float4*>(x);
#pragma unroll
        for (int u = 0; u < (BM * DIM / 4) / TH; u++) {   // 8 iters
            int idx = u * TH + tid;
            int row = idx & (BM - 1);
            int pp  = idx >> 7;                           // 0..15 (float4 index)
            float4 v = gx4[(size_t)(gn0 + row) * (DIM / 4) + pp];
            xs[(2 * pp)     * BM + row] = pack2(v.x, v.y);
            xs[(2 * pp + 1) * BM + row] = pack2(v.z, v.w);
        }
    }

    float best[4];
    int   bidx[4];
#pragma unroll
    for (int i = 0; i < 4; i++) { best[i] = FLT_MAX; bidx[i] = 0; }

    const float4* gc4 = reinterpret_cast<const float4*>(cb);

    for (int kt = 0; kt < K_CODES / BK; kt++) {
        __syncthreads();   // protect cs reuse (and xs fill on first iter)
        // ---- Fill c tile: cs[p][c]. Conflict-free smem writes (lanes -> consecutive codes).
#pragma unroll
        for (int u = 0; u < (BK * DIM / 4) / TH; u++) {   // 4 iters
            int idx = u * TH + tid;
            int c   = idx & (BK - 1);
            int pp  = idx >> 6;                           // 0..15
            float4 v = gc4[(size_t)(kt * BK + c) * (DIM / 4) + pp];
            cs[(2 * pp)     * BK + c] = pack2(v.x, v.y);
            cs[(2 * pp + 1) * BK + c] = pack2(v.z, v.w);
        }
        // ||c||^2 for this thread's 8 columns (L1-resident, 32B/warp broadcast)
        float cq[8];
#pragma unroll
        for (int j = 0; j < 8; j++)
            cq[j] = __ldg(&g_csq[kt * BK + j * 8 + colgrp]);
        __syncthreads();

        unsigned long long acc[4][8];
#pragma unroll
        for (int i = 0; i < 4; i++)
#pragma unroll
            for (int j = 0; j < 8; j++) acc[i][j] = 0ull;

        // Main loop. a: 4 distinct addrs/warp (banks 0/8/16/24, 8-way bcast) -> 1 cyc.
        //            b: lane-contiguous 8B -> 1 cyc. 12 LDS vs 16 FFMA2-issue cyc / warp-p.
#pragma unroll 8
        for (int p = 0; p < DP; p++) {
            unsigned long long a[4], b[8];
#pragma unroll
            for (int i = 0; i < 4; i++) a[i] = xs[p * BM + row0 + i];
#pragma unroll
            for (int j = 0; j < 8; j++) b[j] = cs[p * BK + j * 8 + colgrp];
#pragma unroll
            for (int i = 0; i < 4; i++)
#pragma unroll
                for (int j = 0; j < 8; j++) ffma2(acc[i][j], a[i], b[j]);
        }

        // Per-tile compare. j ascending => ascending code index within thread (stride 8).
        const int gk0 = kt * BK + colgrp;
#pragma unroll
        for (int i = 0; i < 4; i++) {
#pragma unroll
            for (int j = 0; j < 8; j++) {
                unsigned long long v = acc[i][j];
                float lo = __uint_as_float((unsigned)(v & 0xffffffffull));
                float hi = __uint_as_float((unsigned)(v >> 32));
                float dot = lo + hi;
                float s = fmaf(-2.f, dot, cq[j]);       // ||c||^2 - 2 x.c
                if (s < best[i]) { best[i] = s; bidx[i] = gk0 + j * 8; }
            }
        }
    }

    // ---- Cross-lane reduce over the 8 colgrp lanes (contiguous lanes 0..7 within
    // each rowgrp octet). Lexicographic (val, idx) min == global first-min.
#pragma unroll
    for (int d = 1; d < 8; d <<= 1) {
#pragma unroll
        for (int i = 0; i < 4; i++) {
            float ov = __shfl_xor_sync(0xffffffffu, best[i], d);
            int   oi = __shfl_xor_sync(0xffffffffu, bidx[i], d);
            if (ov < best[i] || (ov == best[i] && oi < bidx[i])) {
                best[i] = ov; bidx[i] = oi;
            }
        }
    }
    if (colgrp == 0) {
#pragma unroll
        for (int i = 0; i < 4; i++)
            out[gn0 + row0 + i] = (float)bidx[i];   // fp32 output dtype
    }
}

extern "C" void kernel_launch(void* const* d_in, const int* in_sizes, int n_in,
                              void* d_out, int out_size) {
    const float* x  = (const float*)d_in[0];
    const float* cb = (const float*)d_in[1];
    if (n_in >= 2 && in_sizes[0] == K_CODES * DIM && in_sizes[1] == N_ROWS * DIM) {
        const float* t = x; x = cb; cb = t;
    }
    float* out = (float*)d_out;

    csq_kernel<<<K_CODES / 256, 256>>>(cb);
    vq_kernel<<<N_ROWS / BM, TH>>>(x, cb, out);
}